// round 16
// baseline (speedup 1.0000x reference)
#include <cuda_runtime.h>
#include <cuda_bf16.h>
#include <cuda_fp16.h>
#include <math.h>
#include <stdint.h>

// GAT forward, B=4 N=2048 F=128 H=8 D=64 C=32.
// Softmax trick: exp(lrelu(f1_i+f2_j))/exp(f1_i) = (f1_i+f2_j>0) ? exp(f2_j)
//   : exp(-0.8 f1_i)*exp(0.2 f2_j); exp(f1_i) cancels in softmax.
// R16: base = R14 (R15 reverted). All GEMMs single-product fp16 HMMA;
// z via HADD2 tree in the weight phase (no z-MMA); h stored fp16.

#define BB 4
#define NN 2048
#define FF 128
#define DD 64
#define HH 8
#define CC 32
#define HD (HH*DD)

__device__ __align__(16) float2 g_F1R[BB*HH*NN];     // (f1, exp(-0.8 f1))
__device__ __align__(16) uint4  g_F2H[BB*HH*NN/2];   // per j-pair {f2,e,e02} fp16x2
__device__ __align__(16) float2 g_G1R[BB*NN];
__device__ __align__(16) uint4  g_G2H[BB*NN/2];
__device__ unsigned g_adjbT[BB*64*NN];               // bitmask, TRANSPOSED [b][word][row]
__device__ __align__(16) __half g_WhT[BB*HH*DD*NN];      // WhT fp16 [bh][d][j]
__device__ __align__(16) __half g_Wh2T[BB*CC*NN];        // Wh2T fp16 [b][c][j]
__device__ __align__(16) __half g_WT[HH*DD*FF];          // WcatT fp16 [c][f]
__device__ __align__(16) __half g_h[BB*NN*HD];           // h fp16 [bn][hd]
__device__ __align__(16) __half g_WoT[CC*HD];            // WoT fp16 [c][k]

__device__ __forceinline__ uint32_t smem_u32(const void* p) {
    uint32_t a;
    asm("{ .reg .u64 tmp; cvta.to.shared.u64 tmp, %1; cvt.u32.u64 %0, tmp; }"
        : "=r"(a) : "l"(p));
    return a;
}
__device__ __forceinline__ void ldsm_x4(uint32_t* r, uint32_t addr) {
    asm volatile("ldmatrix.sync.aligned.m8n8.x4.shared.b16 {%0,%1,%2,%3}, [%4];"
        : "=r"(r[0]), "=r"(r[1]), "=r"(r[2]), "=r"(r[3]) : "r"(addr));
}
__device__ __forceinline__ void mma16816h(float* c, const uint32_t* a, const uint32_t* b) {
    asm volatile(
        "mma.sync.aligned.m16n8k16.row.col.f32.f16.f16.f32 "
        "{%0,%1,%2,%3}, {%4,%5,%6,%7}, {%8,%9}, {%0,%1,%2,%3};"
        : "+f"(c[0]), "+f"(c[1]), "+f"(c[2]), "+f"(c[3])
        : "r"(a[0]), "r"(a[1]), "r"(a[2]), "r"(a[3]), "r"(b[0]), "r"(b[1]));
}
#define CP_ASYNC16(dst, src) \
    asm volatile("cp.async.cg.shared.global [%0], [%1], 16;" :: "r"(dst), "l"(src))
#define CP_COMMIT() asm volatile("cp.async.commit_group;" ::: "memory")
#define CP_WAIT(n)  asm volatile("cp.async.wait_group %0;" :: "n"(n) : "memory")

__device__ __forceinline__ uint32_t pk_h2(float a, float b) {
    __half2 hp = __floats2half2_rn(a, b);
    return *reinterpret_cast<uint32_t*>(&hp);
}
__device__ __forceinline__ __half2 u2h(uint32_t v) {
    return *reinterpret_cast<__half2*>(&v);
}
__device__ __forceinline__ uint32_t hgt2m(uint32_t a, uint32_t b) {
    return __hgt2_mask(u2h(a), u2h(b));
}
__device__ __forceinline__ uint32_t hmul2u(uint32_t a, uint32_t b) {
    __half2 r = __hmul2(u2h(a), u2h(b));
    return *reinterpret_cast<uint32_t*>(&r);
}
__device__ __forceinline__ uint32_t f2h2(float v) {
    __half2 r = __float2half2_rn(v);
    return *reinterpret_cast<uint32_t*>(&r);
}

// ---------------- KWS: W[h][f][d] -> WcatT[c][f] fp16 ----------------
__global__ __launch_bounds__(256) void kws_split(const float* __restrict__ W) {
    int idx = blockIdx.x*256 + threadIdx.x;      // 0..16383 = c*32 + kg
    int c = idx >> 5, kg = idx & 31;
    int h = c >> 6, d = c & 63;
    float v[4];
    #pragma unroll
    for (int q = 0; q < 4; q++)
        v[q] = W[h*(FF*DD) + (kg*4 + q)*DD + d];
    *reinterpret_cast<uint2*>(g_WT + (size_t)c*FF + kg*4) =
        make_uint2(pk_h2(v[0], v[1]), pk_h2(v[2], v[3]));
}

// ---------------- K4W: Wo[k][c] -> WoT[c][k] fp16 ----------------
__global__ __launch_bounds__(256) void k4w_split(const float* __restrict__ Wo) {
    int idx = blockIdx.x*256 + threadIdx.x;      // 0..4095 = c*128 + kg
    int c = idx >> 7, kg = idx & 127;
    float v[4];
    #pragma unroll
    for (int q = 0; q < 4; q++)
        v[q] = Wo[(kg*4 + q)*CC + c];
    *reinterpret_cast<uint2*>(g_WoT + (size_t)c*HD + kg*4) =
        make_uint2(pk_h2(v[0], v[1]), pk_h2(v[2], v[3]));
}

// ---------------- K0: adjacency -> transposed bitmask (int4 + shfl-or) ----------------
__global__ __launch_bounds__(256) void k0_mask(const int* __restrict__ adj) {
    int gw = (blockIdx.x * 256 + threadIdx.x) >> 5;  // 0..8191 = b*2048+row
    int lane = threadIdx.x & 31;
    int b = gw >> 11, row = gw & 2047;
    const int4* ar4 = reinterpret_cast<const int4*>(adj + (size_t)gw * NN);
    int lg = lane & 7, wsel = lane >> 3;
    #pragma unroll 4
    for (int it = 0; it < 16; it++) {
        int4 v = ar4[it*32 + lane];
        unsigned nib = (v.x > 0 ? 1u : 0u) | (v.y > 0 ? 2u : 0u)
                     | (v.z > 0 ? 4u : 0u) | (v.w > 0 ? 8u : 0u);
        unsigned part = nib << (lg * 4);
        part |= __shfl_xor_sync(0xffffffffu, part, 1);
        part |= __shfl_xor_sync(0xffffffffu, part, 2);
        part |= __shfl_xor_sync(0xffffffffu, part, 4);
        if (lg == 0)
            g_adjbT[((b<<6) + it*4 + wsel)*NN + row] = part;
    }
}

// ---------------- K1: Wh = x @ Wcat (fp16 1-prod HMMA); fused WhT + f1/f2 ----------------
// smem: A @0 (128x72 fp16, 18432); B @18432 (64x72, 9216).
// epilogue overlay: ts[64][132] fp32 @0; a1s @33792; a2s @34048; fse @34304.
#define K1_SMEM 36864
__global__ __launch_bounds__(256) void k1_hmma(const float* __restrict__ x,
                                               const float* __restrict__ a1,
                                               const float* __restrict__ a2) {
    extern __shared__ __align__(16) char smem[];
    uint32_t sb = smem_u32(smem);
    int t = threadIdx.x;
    int warp = t >> 5, lane = t & 31;
    int h = blockIdx.x;
    int m0 = blockIdx.y * 128;
    int b = m0 >> 11, nd0 = m0 & 2047;
    int bh = b*8 + h;

    float acc[8][4];
    #pragma unroll
    for (int n=0;n<8;n++){ acc[n][0]=0.f; acc[n][1]=0.f; acc[n][2]=0.f; acc[n][3]=0.f; }

    uint32_t aRow = (uint32_t)(warp*16 + (lane & 15)) * 144u + ((lane & 16) ? 16u : 0u);
    uint32_t bAddr = sb + 18432u + (uint32_t)(lane & 7) * 144u
                   + ((lane & 16) ? 1152u : 0u) + (uint32_t)(lane & 8) * 2u;

    int rA = t >> 1, hA = t & 1;
    int rB = t >> 2, cB = t & 3;

    #pragma unroll
    for (int kt = 0; kt < 2; kt++) {
        if (kt) __syncthreads();
        int k0 = kt * 64;
        {   // A tile: x fp32 -> fp16
            const float4* px = reinterpret_cast<const float4*>(
                x + (size_t)(m0 + rA)*FF + k0 + hA*32);
            uint32_t off = (uint32_t)rA*144u + (uint32_t)hA*64u;
            #pragma unroll
            for (int q = 0; q < 4; q++) {
                float4 v0 = px[q*2], v1 = px[q*2+1];
                uint4 hw = make_uint4(pk_h2(v0.x, v0.y), pk_h2(v0.z, v0.w),
                                      pk_h2(v1.x, v1.y), pk_h2(v1.z, v1.w));
                *reinterpret_cast<uint4*>(smem + off + q*16) = hw;
            }
        }
        {   // B tile: WcatT fp16
            const __half* ph = g_WT + (size_t)(h*64 + rB)*FF + k0 + cB*16;
            uint32_t off = (uint32_t)rB*144u + (uint32_t)cB*32u;
            *reinterpret_cast<uint4*>(smem + 18432 + off)      =
                *reinterpret_cast<const uint4*>(ph);
            *reinterpret_cast<uint4*>(smem + 18432 + off + 16) =
                *reinterpret_cast<const uint4*>(ph + 8);
        }
        __syncthreads();
        #pragma unroll
        for (int k = 0; k < 4; k++) {
            uint32_t kb = (uint32_t)k * 32u;
            uint32_t ah[4];
            ldsm_x4(ah, sb + aRow + kb);
            #pragma unroll
            for (int q = 0; q < 4; q++) {
                uint32_t bf[4];
                ldsm_x4(bf, bAddr + (uint32_t)q*2304u + kb);
                mma16816h(acc[2*q],   ah, bf);
                mma16816h(acc[2*q+1], ah, bf + 2);
            }
        }
    }
    // ---- fused epilogue: transpose, f1/f2 (+fp16 triplets), WhT fp16 ----
    __syncthreads();
    float* ts = reinterpret_cast<float*>(smem);          // [64 d][132]
    float* a1s = reinterpret_cast<float*>(smem + 33792);
    float* a2s = reinterpret_cast<float*>(smem + 34048);
    float* fse = reinterpret_cast<float*>(smem + 34304); // 3 x 128
    if (t < 64) { a1s[t] = a1[h*DD + t]; a2s[t] = a2[h*DD + t]; }
    int r0 = warp*16 + (lane >> 2);
    int r1 = r0 + 8;
    #pragma unroll
    for (int n = 0; n < 8; n++) {
        int c = n*8 + (lane & 3)*2;
        ts[c*132 + r0]     = acc[n][0];
        ts[(c+1)*132 + r0] = acc[n][1];
        ts[c*132 + r1]     = acc[n][2];
        ts[(c+1)*132 + r1] = acc[n][3];
    }
    __syncthreads();
    if (t < 128) {
        float f1 = 0.f, f2 = 0.f;
        #pragma unroll
        for (int d = 0; d < 64; d++) {
            float wv = ts[d*132 + t];
            f1 += wv * a1s[d];
            f2 += wv * a2s[d];
        }
        int tid = bh*NN + nd0 + t;
        g_F1R[tid] = make_float2(f1, expf(-0.8f*f1));
        fse[t]       = f2;
        fse[128 + t] = expf(f2);
        fse[256 + t] = expf(0.2f*f2);
    }
    #pragma unroll
    for (int q = 0; q < 4; q++) {
        int task = t + q*256;
        int d = task >> 4, nc = task & 15;
        uint32_t hw[4];
        #pragma unroll
        for (int p = 0; p < 4; p++)
            hw[p] = pk_h2(ts[d*132 + nc*8 + 2*p], ts[d*132 + nc*8 + 2*p + 1]);
        size_t off = ((size_t)bh*DD + d)*NN + nd0 + nc*8;
        *reinterpret_cast<uint4*>(g_WhT + off) = *reinterpret_cast<uint4*>(hw);
    }
    __syncthreads();
    if (t < 64) {
        uint4 o;
        o.x = pk_h2(fse[2*t],       fse[2*t + 1]);
        o.y = pk_h2(fse[128 + 2*t], fse[128 + 2*t + 1]);
        o.z = pk_h2(fse[256 + 2*t], fse[256 + 2*t + 1]);
        o.w = 0;
        g_F2H[(size_t)bh*(NN/2) + nd0/2 + t] = o;
    }
}

// ---------------- K3: layer-1 attention, fp16 HMMA, h2 weights + HADD2 z ----------------
// smem: A @0 (128x72 fp16, 18432); B buf0 @18432 (9216); buf1 @27648;
// f2s @36864 (1KB); zp @37888 (2x128 fl = 1KB). Total 38912.
#define K3_SMEM 38912
__global__ __launch_bounds__(256) void k3_attn1_mma() {
    extern __shared__ __align__(16) char smem[];
    char* Ahp = smem;
    uint4* f2s = reinterpret_cast<uint4*>(smem + 36864);
    float* zp = reinterpret_cast<float*>(smem + 37888);
    uint32_t sb = smem_u32(smem);

    int t = threadIdx.x;
    int warp = t >> 5, lane = t & 31;
    int i0 = blockIdx.x * 128;
    int h = blockIdx.y, b = blockIdx.z;
    int bh = (b<<3) + h;

    int i = t & 127, jh = t >> 7;
    float2 f1r = g_F1R[bh*NN + i0 + i];
    uint32_t negf1h = f2h2(-f1r.x);
    uint32_t rmulh  = f2h2(f1r.y);
    const __half* bsrc = g_WhT + (size_t)bh*DD*NN;
    const uint4* f2g = g_F2H + (size_t)bh*(NN/2);
    float zacc = 0.f;

    float acc[8][4];
    #pragma unroll
    for (int n=0;n<8;n++){ acc[n][0]=0.f; acc[n][1]=0.f; acc[n][2]=0.f; acc[n][3]=0.f; }

    int m0 = warp * 16;
    uint32_t aRow = (uint32_t)(m0 + (lane & 15)) * 144u + ((lane & 16) ? 16u : 0u);
    uint32_t bFrag = (uint32_t)(lane & 7) * 144u + ((lane & 16) ? 1152u : 0u)
                   + (uint32_t)(lane & 8) * 2u;

    int dB = t >> 2, cB = t & 3;
    const __half* pB = bsrc + (size_t)dB*NN + cB*16;
    uint32_t bStOff = (uint32_t)dB*144u + (uint32_t)cB*32u;

    {
        uint32_t d0 = sb + 18432u + bStOff;
        CP_ASYNC16(d0,      pB);
        CP_ASYNC16(d0 + 16, pB + 8);
        CP_COMMIT();
    }
    if (t < 32) f2s[t] = __ldg(&f2g[t]);
    __syncthreads();

    for (int jt = 0; jt < 32; jt++) {
        int buf = jt & 1;
        if (jt) __syncthreads();
        if (jt < 31) {
            uint32_t dN = sb + 18432u + (uint32_t)(buf^1)*9216u + bStOff;
            const __half* s = pB + (jt+1)*64;
            CP_ASYNC16(dN,      s);
            CP_ASYNC16(dN + 16, s + 8);
            CP_COMMIT();
        }
        // ---- h2 weight phase + HADD2 z ----
        unsigned bw = g_adjbT[((b<<6) + jt*2 + jh)*NN + i0 + i];
        const uint4* fp = &f2s[buf*32 + jh*16];
        #pragma unroll
        for (int pq = 0; pq < 4; pq++) {
            uint32_t wv[4];
            #pragma unroll
            for (int p = 0; p < 4; p++) {
                uint4 tr = fp[pq*4 + p];
                uint32_t mgt = hgt2m(tr.x, negf1h);
                uint32_t alt = hmul2u(rmulh, tr.z);
                uint32_t sel = (tr.y & mgt) | (alt & ~mgt);
                uint32_t bits = (bw >> ((pq*4 + p)*2)) & 3u;
                uint32_t am = ((bits & 1u) ? 0xFFFFu : 0u)
                            | ((bits & 2u) ? 0xFFFF0000u : 0u);
                wv[p] = sel & am;
            }
            __half2 s0 = __hadd2(u2h(wv[0]), u2h(wv[1]));
            __half2 s1 = __hadd2(u2h(wv[2]), u2h(wv[3]));
            float2 fz = __half22float2(__hadd2(s0, s1));
            zacc += fz.x + fz.y;
            uint32_t off = (uint32_t)i*144u + (uint32_t)(jh*64 + pq*16);
            *reinterpret_cast<uint4*>(Ahp + off) =
                make_uint4(wv[0], wv[1], wv[2], wv[3]);
        }
        if (jt < 31 && t < 32)
            f2s[(buf^1)*32 + t] = __ldg(&f2g[(jt+1)*32 + t]);
        if (jt < 31) { CP_WAIT(1); } else { CP_WAIT(0); }
        __syncthreads();
        // ---- MMA(jt): 1 product, paired-n LDSM ----
        uint32_t bBase = sb + 18432u + (uint32_t)buf*9216u + bFrag;
        #pragma unroll
        for (int k = 0; k < 4; k++) {
            uint32_t kb = (uint32_t)k * 32u;
            uint32_t ah[4];
            ldsm_x4(ah, sb + aRow + kb);
            #pragma unroll
            for (int q = 0; q < 4; q++) {
                uint32_t bf[4];
                ldsm_x4(bf, bBase + (uint32_t)q*2304u + kb);
                mma16816h(acc[2*q],   ah, bf);
                mma16816h(acc[2*q+1], ah, bf + 2);
            }
        }
    }
    zp[jh*128 + i] = zacc;
    __syncthreads();
    // ---- epilogue: normalize + ELU; h fp16 ----
    int r0 = m0 + (lane >> 2);
    int r1 = r0 + 8;
    float z0 = zp[r0] + zp[128 + r0];   if (z0 < 1e-30f) z0 = 1.f;
    float z1 = zp[r1] + zp[128 + r1];   if (z1 < 1e-30f) z1 = 1.f;
    float invz0 = 1.f / z0, invz1 = 1.f / z1;
    size_t base0 = (size_t)(b*NN + i0 + r0)*HD + h*DD + (lane & 3)*2;
    size_t base1 = (size_t)(b*NN + i0 + r1)*HD + h*DD + (lane & 3)*2;
    #pragma unroll
    for (int n = 0; n < 8; n++) {
        float v0 = acc[n][0] * invz0, v1 = acc[n][1] * invz0;
        float v2 = acc[n][2] * invz1, v3 = acc[n][3] * invz1;
        v0 = v0 > 0.f ? v0 : expm1f(v0);
        v1 = v1 > 0.f ? v1 : expm1f(v1);
        v2 = v2 > 0.f ? v2 : expm1f(v2);
        v3 = v3 > 0.f ? v3 : expm1f(v3);
        *reinterpret_cast<uint32_t*>(g_h + base0 + n*8) = pk_h2(v0, v1);
        *reinterpret_cast<uint32_t*>(g_h + base1 + n*8) = pk_h2(v2, v3);
    }
}

// ---------------- K4: Wh2 = h @ Wo (fp16 1-prod HMMA); fused Wh2T + g1/g2 ----------------
__global__ __launch_bounds__(256) void k4_hmma(const float* __restrict__ ao1,
                                               const float* __restrict__ ao2) {
    __shared__ __align__(16) char Ahp[64*144];    // h fp16 [64][72]
    __shared__ __align__(16) char Bs[32*144];     // WoT fp16 [32][72]
    uint32_t sbA = smem_u32(Ahp);
    uint32_t sbB = smem_u32(Bs);

    int t = threadIdx.x;
    int warp = t >> 5, lane = t & 31;
    int m0 = blockIdx.x * 64;
    int b = m0 >> 11, nd0 = m0 & 2047;
    int mt = warp >> 1, nh = warp & 1;

    float acc[2][4];
    acc[0][0]=0.f; acc[0][1]=0.f; acc[0][2]=0.f; acc[0][3]=0.f;
    acc[1][0]=0.f; acc[1][1]=0.f; acc[1][2]=0.f; acc[1][3]=0.f;

    uint32_t aRow = (uint32_t)(mt*16 + (lane & 15)) * 144u + ((lane & 16) ? 16u : 0u);
    uint32_t bAddr = sbB + (uint32_t)(lane & 7) * 144u + ((lane & 16) ? 1152u : 0u)
                   + (uint32_t)(lane & 8) * 2u + (uint32_t)nh * 2304u;

    int rA = t >> 2, cA = t & 3;
    int rB = t >> 3, cB = t & 7;

    #pragma unroll
    for (int kt = 0; kt < 8; kt++) {
        if (kt) __syncthreads();
        int k0 = kt * 64;
        {
            const __half* ph = g_h + (size_t)(m0 + rA)*HD + k0 + cA*16;
            uint32_t off = (uint32_t)rA*144u + (uint32_t)cA*32u;
            *reinterpret_cast<uint4*>(Ahp + off)      = *reinterpret_cast<const uint4*>(ph);
            *reinterpret_cast<uint4*>(Ahp + off + 16) = *reinterpret_cast<const uint4*>(ph + 8);
        }
        {
            const __half* ph = g_WoT + (size_t)rB*HD + k0 + cB*8;
            *reinterpret_cast<uint4*>(Bs + (uint32_t)rB*144u + (uint32_t)cB*16u) =
                *reinterpret_cast<const uint4*>(ph);
        }
        __syncthreads();
        #pragma unroll
        for (int k = 0; k < 4; k++) {
            uint32_t kb = (uint32_t)k * 32u;
            uint32_t ah[4];
            ldsm_x4(ah, sbA + aRow + kb);
            uint32_t bf[4];
            ldsm_x4(bf, bAddr + kb);
            mma16816h(acc[0], ah, bf);
            mma16816h(acc[1], ah, bf + 2);
        }
    }
    // ---- fused epilogue: transpose tile, g1/g2 (+fp16 triplets), Wh2T fp16 ----
    __syncthreads();
    float* ts2 = reinterpret_cast<float*>(Ahp);          // [32 c][68] (8704B)
    float* ao1s = reinterpret_cast<float*>(Bs);          // 32
    float* ao2s = reinterpret_cast<float*>(Bs + 128);    // 32
    float* fse2 = reinterpret_cast<float*>(Bs + 256);    // 3 x 64
    if (t < 32) { ao1s[t] = ao1[t]; ao2s[t] = ao2[t]; }
    int r0 = mt*16 + (lane >> 2);
    int r1 = r0 + 8;
    #pragma unroll
    for (int n = 0; n < 2; n++) {
        int c = nh*16 + n*8 + (lane & 3)*2;
        ts2[c*68 + r0]     = acc[n][0];
        ts2[(c+1)*68 + r0] = acc[n][1];
        ts2[c*68 + r1]     = acc[n][2];
        ts2[(c+1)*68 + r1] = acc[n][3];
    }
    __syncthreads();
    if (t < 64) {
        float g1 = 0.f, g2 = 0.f;
        #pragma unroll
        for (int c = 0; c < 32; c++) {
            float wv = ts2[c*68 + t];
            g1 += wv * ao1s[c];
            g2 += wv * ao2s[c];
        }
        int tid = b*NN + nd0 + t;
        g_G1R[tid] = make_float2(g1, expf(-0.8f*g1));
        fse2[t]       = g2;
        fse2[64 + t]  = expf(g2);
        fse2[128 + t] = expf(0.2f*g2);
    }
    {
        int c = t >> 3, nc = t & 7;
        uint32_t hw[4];
        #pragma unroll
        for (int p = 0; p < 4; p++)
            hw[p] = pk_h2(ts2[c*68 + nc*8 + 2*p], ts2[c*68 + nc*8 + 2*p + 1]);
        size_t off = ((size_t)(b*CC) + c)*NN + nd0 + nc*8;
        *reinterpret_cast<uint4*>(g_Wh2T + off) = *reinterpret_cast<uint4*>(hw);
    }
    __syncthreads();
    if (t < 32) {
        uint4 o;
        o.x = pk_h2(fse2[2*t],       fse2[2*t + 1]);
        o.y = pk_h2(fse2[64 + 2*t],  fse2[64 + 2*t + 1]);
        o.z = pk_h2(fse2[128 + 2*t], fse2[128 + 2*t + 1]);
        o.w = 0;
        g_G2H[(size_t)b*(NN/2) + nd0/2 + t] = o;
    }
}

// ---------------- K5: layer-2 attention, fp16 HMMA, h2 weights + HADD2 z ----------------
__global__ __launch_bounds__(256) void k5_attn2_mma(float* __restrict__ out) {
    __shared__ __align__(16) char Ahp[64*144];    // w fp16 [64][72]
    __shared__ __align__(16) char Bs[32*144];     // Wh2T fp16 [32][72]
    __shared__ __align__(16) uint4 g2s[64];       // staged triplets, 2 bufs of 32
    __shared__ float zp[4][64];
    uint32_t sbA = smem_u32(Ahp);
    uint32_t sbB = smem_u32(Bs);

    int t = threadIdx.x;
    int warp = t >> 5, lane = t & 31;
    int i0 = blockIdx.x * 64;
    int b = blockIdx.y;

    int i = t & 63, jq = t >> 6;
    float2 g1r = g_G1R[b*NN + i0 + i];
    uint32_t negg = f2h2(-g1r.x);
    uint32_t rmulh = f2h2(g1r.y);
    const __half* bsrc = g_Wh2T + (size_t)(b*CC)*NN;
    const uint4* g2g = g_G2H + (size_t)b*(NN/2);
    float zacc = 0.f;

    int mt = warp >> 1, nh = warp & 1;
    float acc[2][4];
    acc[0][0]=0.f; acc[0][1]=0.f; acc[0][2]=0.f; acc[0][3]=0.f;
    acc[1][0]=0.f; acc[1][1]=0.f; acc[1][2]=0.f; acc[1][3]=0.f;

    uint32_t aRow = (uint32_t)(mt*16 + (lane & 15)) * 144u + ((lane & 16) ? 16u : 0u);
    uint32_t bAddr = sbB + (uint32_t)(lane & 7) * 144u + ((lane & 16) ? 1152u : 0u)
                   + (uint32_t)(lane & 8) * 2u + (uint32_t)nh * 2304u;

    if (t < 32) g2s[t] = __ldg(&g2g[t]);
    __syncthreads();

    for (int jt = 0; jt < 32; jt++) {
        int buf = jt & 1;
        if (jt) __syncthreads();
        int j0 = jt * 64;
        unsigned bwf = g_adjbT[((b<<6) + jt*2 + (jq>>1))*NN + i0 + i];
        unsigned bw = (bwf >> ((jq & 1)*16)) & 0xFFFFu;
        const uint4* gp = &g2s[buf*32 + jq*8];
        #pragma unroll
        for (int pq = 0; pq < 2; pq++) {
            uint32_t wv[4];
            #pragma unroll
            for (int p = 0; p < 4; p++) {
                uint4 tr = gp[pq*4 + p];
                uint32_t mgt = hgt2m(tr.x, negg);
                uint32_t alt = hmul2u(rmulh, tr.z);
                uint32_t sel = (tr.y & mgt) | (alt & ~mgt);
                uint32_t bits = (bw >> ((pq*4 + p)*2)) & 3u;
                uint32_t am = ((bits & 1u) ? 0xFFFFu : 0u)
                            | ((bits & 2u) ? 0xFFFF0000u : 0u);
                wv[p] = sel & am;
            }
            __half2 s0 = __hadd2(u2h(wv[0]), u2h(wv[1]));
            __half2 s1 = __hadd2(u2h(wv[2]), u2h(wv[3]));
            float2 fz = __half22float2(__hadd2(s0, s1));
            zacc += fz.x + fz.y;
            uint32_t off = (uint32_t)i*144u + (uint32_t)(jq*32 + pq*16);
            *reinterpret_cast<uint4*>(Ahp + off) =
                make_uint4(wv[0], wv[1], wv[2], wv[3]);
        }
        {
            int c = t >> 3, ch = t & 7;
            uint4 v = *reinterpret_cast<const uint4*>(bsrc + (size_t)c*NN + j0 + ch*8);
            *reinterpret_cast<uint4*>(Bs + (uint32_t)c*144u + (uint32_t)ch*16u) = v;
        }
        if (jt < 31 && t < 32)
            g2s[(buf^1)*32 + t] = __ldg(&g2g[(jt+1)*32 + t]);
        __syncthreads();
        #pragma unroll
        for (int k = 0; k < 4; k++) {
            uint32_t kb = (uint32_t)k * 32u;
            uint32_t ah[4];
            ldsm_x4(ah, sbA + aRow + kb);
            uint32_t bf[4];
            ldsm_x4(bf, bAddr + kb);
            mma16816h(acc[0], ah, bf);
            mma16816h(acc[1], ah, bf + 2);
        }
    }
    zp[jq][i] = zacc;
    __syncthreads();
    int r0 = mt*16 + (lane >> 2);
    int r1 = r0 + 8;
    float z0 = zp[0][r0] + zp[1][r0] + zp[2][r0] + zp[3][r0];
    float z1 = zp[0][r1] + zp[1][r1] + zp[2][r1] + zp[3][r1];
    if (z0 < 1e-30f) z0 = 1.f;
    if (z1 < 1e-30f) z1 = 1.f;
    float invz0 = 1.f / z0, invz1 = 1.f / z1;
    #pragma unroll
    for (int n = 0; n < 2; n++) {
        int c0 = nh*16 + n*8 + (lane & 3)*2;
        float2 o0 = make_float2(acc[n][0]*invz0, acc[n][1]*invz0);
        float2 o1 = make_float2(acc[n][2]*invz1, acc[n][3]*invz1);
        *reinterpret_cast<float2*>(&out[(size_t)(b*NN + i0 + r0)*CC + c0]) = o0;
        *reinterpret_cast<float2*>(&out[(size_t)(b*NN + i0 + r1)*CC + c0]) = o1;
    }
}

extern "C" void kernel_launch(void* const* d_in, const int* in_sizes, int n_in,
                              void* d_out, int out_size) {
    const float* x   = (const float*)d_in[0];
    const int*   adj = (const int*)  d_in[1];
    const float* W   = (const float*)d_in[2];
    const float* a1  = (const float*)d_in[3];
    const float* a2  = (const float*)d_in[4];
    const float* Wo  = (const float*)d_in[5];
    const float* ao1 = (const float*)d_in[6];
    const float* ao2 = (const float*)d_in[7];
    float* out = (float*)d_out;

    cudaFuncSetAttribute(k3_attn1_mma,
                         cudaFuncAttributeMaxDynamicSharedMemorySize, K3_SMEM);
    cudaFuncSetAttribute(k1_hmma,
                         cudaFuncAttributeMaxDynamicSharedMemorySize, K1_SMEM);

    kws_split<<<64, 256>>>(W);                        // W -> WcatT fp16
    k4w_split<<<16, 256>>>(Wo);                       // Wo -> WoT fp16
    k0_mask<<<1024, 256>>>(adj);                      // adj -> transposed bitmask
    k1_hmma<<<dim3(8, 64), 256, K1_SMEM>>>(x, a1, a2);// Wh + WhT fp16 + f-triplets
    k3_attn1_mma<<<dim3(16, 8, 4), 256, K3_SMEM>>>(); // layer-1 attn (1-prod fp16)
    k4_hmma<<<128, 256>>>(ao1, ao2);                  // Wh2T fp16 + g-triplets
    k5_attn2_mma<<<dim3(32, 4), 256>>>(out);          // layer-2 attn (1-prod fp16)
}

// round 17
// speedup vs baseline: 1.0983x; 1.0983x over previous
#include <cuda_runtime.h>
#include <cuda_bf16.h>
#include <cuda_fp16.h>
#include <math.h>
#include <stdint.h>

// GAT forward, B=4 N=2048 F=128 H=8 D=64 C=32.
// Softmax trick: exp(lrelu(f1_i+f2_j))/exp(f1_i) = (f1_i+f2_j>0) ? exp(f2_j)
//   : exp(-0.8 f1_i)*exp(0.2 f2_j); exp(f1_i) cancels in softmax.
// R17: R16's fp16 1-product k1/k4 + fp16 h KEPT; k3/k5 z reverted to the
// ones-column MMA (R14) — HADD2 z tree was on the busy issue path, z-MMA
// rides the tensor pipe's slack.

#define BB 4
#define NN 2048
#define FF 128
#define DD 64
#define HH 8
#define CC 32
#define HD (HH*DD)

__device__ __align__(16) float2 g_F1R[BB*HH*NN];     // (f1, exp(-0.8 f1))
__device__ __align__(16) uint4  g_F2H[BB*HH*NN/2];   // per j-pair {f2,e,e02} fp16x2
__device__ __align__(16) float2 g_G1R[BB*NN];
__device__ __align__(16) uint4  g_G2H[BB*NN/2];
__device__ unsigned g_adjbT[BB*64*NN];               // bitmask, TRANSPOSED [b][word][row]
__device__ __align__(16) __half g_WhT[BB*HH*DD*NN];      // WhT fp16 [bh][d][j]
__device__ __align__(16) __half g_Wh2T[BB*CC*NN];        // Wh2T fp16 [b][c][j]
__device__ __align__(16) __half g_WT[HH*DD*FF];          // WcatT fp16 [c][f]
__device__ __align__(16) __half g_h[BB*NN*HD];           // h fp16 [bn][hd]
__device__ __align__(16) __half g_WoT[CC*HD];            // WoT fp16 [c][k]

__device__ __forceinline__ uint32_t smem_u32(const void* p) {
    uint32_t a;
    asm("{ .reg .u64 tmp; cvta.to.shared.u64 tmp, %1; cvt.u32.u64 %0, tmp; }"
        : "=r"(a) : "l"(p));
    return a;
}
__device__ __forceinline__ void ldsm_x4(uint32_t* r, uint32_t addr) {
    asm volatile("ldmatrix.sync.aligned.m8n8.x4.shared.b16 {%0,%1,%2,%3}, [%4];"
        : "=r"(r[0]), "=r"(r[1]), "=r"(r[2]), "=r"(r[3]) : "r"(addr));
}
__device__ __forceinline__ void mma16816h(float* c, const uint32_t* a, const uint32_t* b) {
    asm volatile(
        "mma.sync.aligned.m16n8k16.row.col.f32.f16.f16.f32 "
        "{%0,%1,%2,%3}, {%4,%5,%6,%7}, {%8,%9}, {%0,%1,%2,%3};"
        : "+f"(c[0]), "+f"(c[1]), "+f"(c[2]), "+f"(c[3])
        : "r"(a[0]), "r"(a[1]), "r"(a[2]), "r"(a[3]), "r"(b[0]), "r"(b[1]));
}
#define CP_ASYNC16(dst, src) \
    asm volatile("cp.async.cg.shared.global [%0], [%1], 16;" :: "r"(dst), "l"(src))
#define CP_COMMIT() asm volatile("cp.async.commit_group;" ::: "memory")
#define CP_WAIT(n)  asm volatile("cp.async.wait_group %0;" :: "n"(n) : "memory")

__device__ __forceinline__ uint32_t pk_h2(float a, float b) {
    __half2 hp = __floats2half2_rn(a, b);
    return *reinterpret_cast<uint32_t*>(&hp);
}
__device__ __forceinline__ __half2 u2h(uint32_t v) {
    return *reinterpret_cast<__half2*>(&v);
}
__device__ __forceinline__ uint32_t hgt2m(uint32_t a, uint32_t b) {
    return __hgt2_mask(u2h(a), u2h(b));
}
__device__ __forceinline__ uint32_t hmul2u(uint32_t a, uint32_t b) {
    __half2 r = __hmul2(u2h(a), u2h(b));
    return *reinterpret_cast<uint32_t*>(&r);
}
__device__ __forceinline__ uint32_t f2h2(float v) {
    __half2 r = __float2half2_rn(v);
    return *reinterpret_cast<uint32_t*>(&r);
}

// ---------------- KWS: W[h][f][d] -> WcatT[c][f] fp16 ----------------
__global__ __launch_bounds__(256) void kws_split(const float* __restrict__ W) {
    int idx = blockIdx.x*256 + threadIdx.x;      // 0..16383 = c*32 + kg
    int c = idx >> 5, kg = idx & 31;
    int h = c >> 6, d = c & 63;
    float v[4];
    #pragma unroll
    for (int q = 0; q < 4; q++)
        v[q] = W[h*(FF*DD) + (kg*4 + q)*DD + d];
    *reinterpret_cast<uint2*>(g_WT + (size_t)c*FF + kg*4) =
        make_uint2(pk_h2(v[0], v[1]), pk_h2(v[2], v[3]));
}

// ---------------- K4W: Wo[k][c] -> WoT[c][k] fp16 ----------------
__global__ __launch_bounds__(256) void k4w_split(const float* __restrict__ Wo) {
    int idx = blockIdx.x*256 + threadIdx.x;      // 0..4095 = c*128 + kg
    int c = idx >> 7, kg = idx & 127;
    float v[4];
    #pragma unroll
    for (int q = 0; q < 4; q++)
        v[q] = Wo[(kg*4 + q)*CC + c];
    *reinterpret_cast<uint2*>(g_WoT + (size_t)c*HD + kg*4) =
        make_uint2(pk_h2(v[0], v[1]), pk_h2(v[2], v[3]));
}

// ---------------- K0: adjacency -> transposed bitmask (int4 + shfl-or) ----------------
__global__ __launch_bounds__(256) void k0_mask(const int* __restrict__ adj) {
    int gw = (blockIdx.x * 256 + threadIdx.x) >> 5;  // 0..8191 = b*2048+row
    int lane = threadIdx.x & 31;
    int b = gw >> 11, row = gw & 2047;
    const int4* ar4 = reinterpret_cast<const int4*>(adj + (size_t)gw * NN);
    int lg = lane & 7, wsel = lane >> 3;
    #pragma unroll 4
    for (int it = 0; it < 16; it++) {
        int4 v = ar4[it*32 + lane];
        unsigned nib = (v.x > 0 ? 1u : 0u) | (v.y > 0 ? 2u : 0u)
                     | (v.z > 0 ? 4u : 0u) | (v.w > 0 ? 8u : 0u);
        unsigned part = nib << (lg * 4);
        part |= __shfl_xor_sync(0xffffffffu, part, 1);
        part |= __shfl_xor_sync(0xffffffffu, part, 2);
        part |= __shfl_xor_sync(0xffffffffu, part, 4);
        if (lg == 0)
            g_adjbT[((b<<6) + it*4 + wsel)*NN + row] = part;
    }
}

// ---------------- K1: Wh = x @ Wcat (fp16 1-prod HMMA); fused WhT + f1/f2 ----------------
// smem: A @0 (128x72 fp16, 18432); B @18432 (64x72, 9216).
// epilogue overlay: ts[64][132] fp32 @0; a1s @33792; a2s @34048; fse @34304.
#define K1_SMEM 36864
__global__ __launch_bounds__(256) void k1_hmma(const float* __restrict__ x,
                                               const float* __restrict__ a1,
                                               const float* __restrict__ a2) {
    extern __shared__ __align__(16) char smem[];
    uint32_t sb = smem_u32(smem);
    int t = threadIdx.x;
    int warp = t >> 5, lane = t & 31;
    int h = blockIdx.x;
    int m0 = blockIdx.y * 128;
    int b = m0 >> 11, nd0 = m0 & 2047;
    int bh = b*8 + h;

    float acc[8][4];
    #pragma unroll
    for (int n=0;n<8;n++){ acc[n][0]=0.f; acc[n][1]=0.f; acc[n][2]=0.f; acc[n][3]=0.f; }

    uint32_t aRow = (uint32_t)(warp*16 + (lane & 15)) * 144u + ((lane & 16) ? 16u : 0u);
    uint32_t bAddr = sb + 18432u + (uint32_t)(lane & 7) * 144u
                   + ((lane & 16) ? 1152u : 0u) + (uint32_t)(lane & 8) * 2u;

    int rA = t >> 1, hA = t & 1;
    int rB = t >> 2, cB = t & 3;

    #pragma unroll
    for (int kt = 0; kt < 2; kt++) {
        if (kt) __syncthreads();
        int k0 = kt * 64;
        {   // A tile: x fp32 -> fp16
            const float4* px = reinterpret_cast<const float4*>(
                x + (size_t)(m0 + rA)*FF + k0 + hA*32);
            uint32_t off = (uint32_t)rA*144u + (uint32_t)hA*64u;
            #pragma unroll
            for (int q = 0; q < 4; q++) {
                float4 v0 = px[q*2], v1 = px[q*2+1];
                uint4 hw = make_uint4(pk_h2(v0.x, v0.y), pk_h2(v0.z, v0.w),
                                      pk_h2(v1.x, v1.y), pk_h2(v1.z, v1.w));
                *reinterpret_cast<uint4*>(smem + off + q*16) = hw;
            }
        }
        {   // B tile: WcatT fp16
            const __half* ph = g_WT + (size_t)(h*64 + rB)*FF + k0 + cB*16;
            uint32_t off = (uint32_t)rB*144u + (uint32_t)cB*32u;
            *reinterpret_cast<uint4*>(smem + 18432 + off)      =
                *reinterpret_cast<const uint4*>(ph);
            *reinterpret_cast<uint4*>(smem + 18432 + off + 16) =
                *reinterpret_cast<const uint4*>(ph + 8);
        }
        __syncthreads();
        #pragma unroll
        for (int k = 0; k < 4; k++) {
            uint32_t kb = (uint32_t)k * 32u;
            uint32_t ah[4];
            ldsm_x4(ah, sb + aRow + kb);
            #pragma unroll
            for (int q = 0; q < 4; q++) {
                uint32_t bf[4];
                ldsm_x4(bf, bAddr + (uint32_t)q*2304u + kb);
                mma16816h(acc[2*q],   ah, bf);
                mma16816h(acc[2*q+1], ah, bf + 2);
            }
        }
    }
    // ---- fused epilogue: transpose, f1/f2 (+fp16 triplets), WhT fp16 ----
    __syncthreads();
    float* ts = reinterpret_cast<float*>(smem);          // [64 d][132]
    float* a1s = reinterpret_cast<float*>(smem + 33792);
    float* a2s = reinterpret_cast<float*>(smem + 34048);
    float* fse = reinterpret_cast<float*>(smem + 34304); // 3 x 128
    if (t < 64) { a1s[t] = a1[h*DD + t]; a2s[t] = a2[h*DD + t]; }
    int r0 = warp*16 + (lane >> 2);
    int r1 = r0 + 8;
    #pragma unroll
    for (int n = 0; n < 8; n++) {
        int c = n*8 + (lane & 3)*2;
        ts[c*132 + r0]     = acc[n][0];
        ts[(c+1)*132 + r0] = acc[n][1];
        ts[c*132 + r1]     = acc[n][2];
        ts[(c+1)*132 + r1] = acc[n][3];
    }
    __syncthreads();
    if (t < 128) {
        float f1 = 0.f, f2 = 0.f;
        #pragma unroll
        for (int d = 0; d < 64; d++) {
            float wv = ts[d*132 + t];
            f1 += wv * a1s[d];
            f2 += wv * a2s[d];
        }
        int tid = bh*NN + nd0 + t;
        g_F1R[tid] = make_float2(f1, expf(-0.8f*f1));
        fse[t]       = f2;
        fse[128 + t] = expf(f2);
        fse[256 + t] = expf(0.2f*f2);
    }
    #pragma unroll
    for (int q = 0; q < 4; q++) {
        int task = t + q*256;
        int d = task >> 4, nc = task & 15;
        uint32_t hw[4];
        #pragma unroll
        for (int p = 0; p < 4; p++)
            hw[p] = pk_h2(ts[d*132 + nc*8 + 2*p], ts[d*132 + nc*8 + 2*p + 1]);
        size_t off = ((size_t)bh*DD + d)*NN + nd0 + nc*8;
        *reinterpret_cast<uint4*>(g_WhT + off) = *reinterpret_cast<uint4*>(hw);
    }
    __syncthreads();
    if (t < 64) {
        uint4 o;
        o.x = pk_h2(fse[2*t],       fse[2*t + 1]);
        o.y = pk_h2(fse[128 + 2*t], fse[128 + 2*t + 1]);
        o.z = pk_h2(fse[256 + 2*t], fse[256 + 2*t + 1]);
        o.w = 0;
        g_F2H[(size_t)bh*(NN/2) + nd0/2 + t] = o;
    }
}

// ---------------- K3: layer-1 attention, fp16 HMMA, h2 weights, z via ones-MMA ----------------
// smem: A @0 (128x72 fp16, 18432); B buf0 @18432 (9216); buf1 @27648;
// f2s @36864 (1KB). Total 37888.
#define K3_SMEM 37888
__global__ __launch_bounds__(256) void k3_attn1_mma() {
    extern __shared__ __align__(16) char smem[];
    char* Ahp = smem;
    uint4* f2s = reinterpret_cast<uint4*>(smem + 36864);
    uint32_t sb = smem_u32(smem);

    int t = threadIdx.x;
    int warp = t >> 5, lane = t & 31;
    int i0 = blockIdx.x * 128;
    int h = blockIdx.y, b = blockIdx.z;
    int bh = (b<<3) + h;

    int i = t & 127, jh = t >> 7;
    float2 f1r = g_F1R[bh*NN + i0 + i];
    uint32_t negf1h = f2h2(-f1r.x);
    uint32_t rmulh  = f2h2(f1r.y);
    const __half* bsrc = g_WhT + (size_t)bh*DD*NN;
    const uint4* f2g = g_F2H + (size_t)bh*(NN/2);

    float acc[8][4];
    #pragma unroll
    for (int n=0;n<8;n++){ acc[n][0]=0.f; acc[n][1]=0.f; acc[n][2]=0.f; acc[n][3]=0.f; }
    float accz[4] = {0.f, 0.f, 0.f, 0.f};
    uint32_t bzf[2];
    bzf[0] = (lane < 4) ? 0x3C003C00u : 0u;   // ones column
    bzf[1] = bzf[0];

    int m0 = warp * 16;
    uint32_t aRow = (uint32_t)(m0 + (lane & 15)) * 144u + ((lane & 16) ? 16u : 0u);
    uint32_t bFrag = (uint32_t)(lane & 7) * 144u + ((lane & 16) ? 1152u : 0u)
                   + (uint32_t)(lane & 8) * 2u;

    int dB = t >> 2, cB = t & 3;
    const __half* pB = bsrc + (size_t)dB*NN + cB*16;
    uint32_t bStOff = (uint32_t)dB*144u + (uint32_t)cB*32u;

    {
        uint32_t d0 = sb + 18432u + bStOff;
        CP_ASYNC16(d0,      pB);
        CP_ASYNC16(d0 + 16, pB + 8);
        CP_COMMIT();
    }
    if (t < 32) f2s[t] = __ldg(&f2g[t]);
    __syncthreads();

    for (int jt = 0; jt < 32; jt++) {
        int buf = jt & 1;
        if (jt) __syncthreads();
        if (jt < 31) {
            uint32_t dN = sb + 18432u + (uint32_t)(buf^1)*9216u + bStOff;
            const __half* s = pB + (jt+1)*64;
            CP_ASYNC16(dN,      s);
            CP_ASYNC16(dN + 16, s + 8);
            CP_COMMIT();
        }
        // ---- h2 weight phase ----
        unsigned bw = g_adjbT[((b<<6) + jt*2 + jh)*NN + i0 + i];
        const uint4* fp = &f2s[buf*32 + jh*16];
        #pragma unroll
        for (int pq = 0; pq < 4; pq++) {
            uint32_t wv[4];
            #pragma unroll
            for (int p = 0; p < 4; p++) {
                uint4 tr = fp[pq*4 + p];
                uint32_t mgt = hgt2m(tr.x, negf1h);
                uint32_t alt = hmul2u(rmulh, tr.z);
                uint32_t sel = (tr.y & mgt) | (alt & ~mgt);
                uint32_t bits = (bw >> ((pq*4 + p)*2)) & 3u;
                uint32_t am = ((bits & 1u) ? 0xFFFFu : 0u)
                            | ((bits & 2u) ? 0xFFFF0000u : 0u);
                wv[p] = sel & am;
            }
            uint32_t off = (uint32_t)i*144u + (uint32_t)(jh*64 + pq*16);
            *reinterpret_cast<uint4*>(Ahp + off) =
                make_uint4(wv[0], wv[1], wv[2], wv[3]);
        }
        if (jt < 31 && t < 32)
            f2s[(buf^1)*32 + t] = __ldg(&f2g[(jt+1)*32 + t]);
        if (jt < 31) { CP_WAIT(1); } else { CP_WAIT(0); }
        __syncthreads();
        // ---- MMA(jt): 1 product + ones-column z ----
        uint32_t bBase = sb + 18432u + (uint32_t)buf*9216u + bFrag;
        #pragma unroll
        for (int k = 0; k < 4; k++) {
            uint32_t kb = (uint32_t)k * 32u;
            uint32_t ah[4];
            ldsm_x4(ah, sb + aRow + kb);
            mma16816h(accz, ah, bzf);
            #pragma unroll
            for (int q = 0; q < 4; q++) {
                uint32_t bf[4];
                ldsm_x4(bf, bBase + (uint32_t)q*2304u + kb);
                mma16816h(acc[2*q],   ah, bf);
                mma16816h(acc[2*q+1], ah, bf + 2);
            }
        }
    }
    // ---- epilogue: z via shfl; normalize + ELU; h fp16 ----
    float z0 = __shfl_sync(0xffffffffu, accz[0], lane & 28);
    float z1 = __shfl_sync(0xffffffffu, accz[2], lane & 28);
    if (z0 < 1e-30f) z0 = 1.f;
    if (z1 < 1e-30f) z1 = 1.f;
    float invz0 = 1.f / z0, invz1 = 1.f / z1;
    int r0 = m0 + (lane >> 2);
    int r1 = r0 + 8;
    size_t base0 = (size_t)(b*NN + i0 + r0)*HD + h*DD + (lane & 3)*2;
    size_t base1 = (size_t)(b*NN + i0 + r1)*HD + h*DD + (lane & 3)*2;
    #pragma unroll
    for (int n = 0; n < 8; n++) {
        float v0 = acc[n][0] * invz0, v1 = acc[n][1] * invz0;
        float v2 = acc[n][2] * invz1, v3 = acc[n][3] * invz1;
        v0 = v0 > 0.f ? v0 : expm1f(v0);
        v1 = v1 > 0.f ? v1 : expm1f(v1);
        v2 = v2 > 0.f ? v2 : expm1f(v2);
        v3 = v3 > 0.f ? v3 : expm1f(v3);
        *reinterpret_cast<uint32_t*>(g_h + base0 + n*8) = pk_h2(v0, v1);
        *reinterpret_cast<uint32_t*>(g_h + base1 + n*8) = pk_h2(v2, v3);
    }
}

// ---------------- K4: Wh2 = h @ Wo (fp16 1-prod HMMA); fused Wh2T + g1/g2 ----------------
__global__ __launch_bounds__(256) void k4_hmma(const float* __restrict__ ao1,
                                               const float* __restrict__ ao2) {
    __shared__ __align__(16) char Ahp[64*144];    // h fp16 [64][72]
    __shared__ __align__(16) char Bs[32*144];     // WoT fp16 [32][72]
    uint32_t sbA = smem_u32(Ahp);
    uint32_t sbB = smem_u32(Bs);

    int t = threadIdx.x;
    int warp = t >> 5, lane = t & 31;
    int m0 = blockIdx.x * 64;
    int b = m0 >> 11, nd0 = m0 & 2047;
    int mt = warp >> 1, nh = warp & 1;

    float acc[2][4];
    acc[0][0]=0.f; acc[0][1]=0.f; acc[0][2]=0.f; acc[0][3]=0.f;
    acc[1][0]=0.f; acc[1][1]=0.f; acc[1][2]=0.f; acc[1][3]=0.f;

    uint32_t aRow = (uint32_t)(mt*16 + (lane & 15)) * 144u + ((lane & 16) ? 16u : 0u);
    uint32_t bAddr = sbB + (uint32_t)(lane & 7) * 144u + ((lane & 16) ? 1152u : 0u)
                   + (uint32_t)(lane & 8) * 2u + (uint32_t)nh * 2304u;

    int rA = t >> 2, cA = t & 3;
    int rB = t >> 3, cB = t & 7;

    #pragma unroll
    for (int kt = 0; kt < 8; kt++) {
        if (kt) __syncthreads();
        int k0 = kt * 64;
        {
            const __half* ph = g_h + (size_t)(m0 + rA)*HD + k0 + cA*16;
            uint32_t off = (uint32_t)rA*144u + (uint32_t)cA*32u;
            *reinterpret_cast<uint4*>(Ahp + off)      = *reinterpret_cast<const uint4*>(ph);
            *reinterpret_cast<uint4*>(Ahp + off + 16) = *reinterpret_cast<const uint4*>(ph + 8);
        }
        {
            const __half* ph = g_WoT + (size_t)rB*HD + k0 + cB*8;
            *reinterpret_cast<uint4*>(Bs + (uint32_t)rB*144u + (uint32_t)cB*16u) =
                *reinterpret_cast<const uint4*>(ph);
        }
        __syncthreads();
        #pragma unroll
        for (int k = 0; k < 4; k++) {
            uint32_t kb = (uint32_t)k * 32u;
            uint32_t ah[4];
            ldsm_x4(ah, sbA + aRow + kb);
            uint32_t bf[4];
            ldsm_x4(bf, bAddr + kb);
            mma16816h(acc[0], ah, bf);
            mma16816h(acc[1], ah, bf + 2);
        }
    }
    // ---- fused epilogue: transpose tile, g1/g2 (+fp16 triplets), Wh2T fp16 ----
    __syncthreads();
    float* ts2 = reinterpret_cast<float*>(Ahp);          // [32 c][68] (8704B)
    float* ao1s = reinterpret_cast<float*>(Bs);          // 32
    float* ao2s = reinterpret_cast<float*>(Bs + 128);    // 32
    float* fse2 = reinterpret_cast<float*>(Bs + 256);    // 3 x 64
    if (t < 32) { ao1s[t] = ao1[t]; ao2s[t] = ao2[t]; }
    int r0 = mt*16 + (lane >> 2);
    int r1 = r0 + 8;
    #pragma unroll
    for (int n = 0; n < 2; n++) {
        int c = nh*16 + n*8 + (lane & 3)*2;
        ts2[c*68 + r0]     = acc[n][0];
        ts2[(c+1)*68 + r0] = acc[n][1];
        ts2[c*68 + r1]     = acc[n][2];
        ts2[(c+1)*68 + r1] = acc[n][3];
    }
    __syncthreads();
    if (t < 64) {
        float g1 = 0.f, g2 = 0.f;
        #pragma unroll
        for (int c = 0; c < 32; c++) {
            float wv = ts2[c*68 + t];
            g1 += wv * ao1s[c];
            g2 += wv * ao2s[c];
        }
        int tid = b*NN + nd0 + t;
        g_G1R[tid] = make_float2(g1, expf(-0.8f*g1));
        fse2[t]       = g2;
        fse2[64 + t]  = expf(g2);
        fse2[128 + t] = expf(0.2f*g2);
    }
    {
        int c = t >> 3, nc = t & 7;
        uint32_t hw[4];
        #pragma unroll
        for (int p = 0; p < 4; p++)
            hw[p] = pk_h2(ts2[c*68 + nc*8 + 2*p], ts2[c*68 + nc*8 + 2*p + 1]);
        size_t off = ((size_t)(b*CC) + c)*NN + nd0 + nc*8;
        *reinterpret_cast<uint4*>(g_Wh2T + off) = *reinterpret_cast<uint4*>(hw);
    }
    __syncthreads();
    if (t < 32) {
        uint4 o;
        o.x = pk_h2(fse2[2*t],       fse2[2*t + 1]);
        o.y = pk_h2(fse2[64 + 2*t],  fse2[64 + 2*t + 1]);
        o.z = pk_h2(fse2[128 + 2*t], fse2[128 + 2*t + 1]);
        o.w = 0;
        g_G2H[(size_t)b*(NN/2) + nd0/2 + t] = o;
    }
}

// ---------------- K5: layer-2 attention, fp16 HMMA, h2 weights, z via ones-MMA ----------------
__global__ __launch_bounds__(256) void k5_attn2_mma(float* __restrict__ out) {
    __shared__ __align__(16) char Ahp[64*144];    // w fp16 [64][72]
    __shared__ __align__(16) char Bs[32*144];     // Wh2T fp16 [32][72]
    __shared__ __align__(16) uint4 g2s[64];       // staged triplets, 2 bufs of 32
    uint32_t sbA = smem_u32(Ahp);
    uint32_t sbB = smem_u32(Bs);

    int t = threadIdx.x;
    int warp = t >> 5, lane = t & 31;
    int i0 = blockIdx.x * 64;
    int b = blockIdx.y;

    int i = t & 63, jq = t >> 6;
    float2 g1r = g_G1R[b*NN + i0 + i];
    uint32_t negg = f2h2(-g1r.x);
    uint32_t rmulh = f2h2(g1r.y);
    const __half* bsrc = g_Wh2T + (size_t)(b*CC)*NN;
    const uint4* g2g = g_G2H + (size_t)b*(NN/2);

    int mt = warp >> 1, nh = warp & 1;
    float acc[2][4];
    acc[0][0]=0.f; acc[0][1]=0.f; acc[0][2]=0.f; acc[0][3]=0.f;
    acc[1][0]=0.f; acc[1][1]=0.f; acc[1][2]=0.f; acc[1][3]=0.f;
    float accz[4] = {0.f, 0.f, 0.f, 0.f};
    uint32_t bzf[2];
    bzf[0] = (lane < 4) ? 0x3C003C00u : 0u;
    bzf[1] = bzf[0];

    uint32_t aRow = (uint32_t)(mt*16 + (lane & 15)) * 144u + ((lane & 16) ? 16u : 0u);
    uint32_t bAddr = sbB + (uint32_t)(lane & 7) * 144u + ((lane & 16) ? 1152u : 0u)
                   + (uint32_t)(lane & 8) * 2u + (uint32_t)nh * 2304u;

    if (t < 32) g2s[t] = __ldg(&g2g[t]);
    __syncthreads();

    for (int jt = 0; jt < 32; jt++) {
        int buf = jt & 1;
        if (jt) __syncthreads();
        int j0 = jt * 64;
        unsigned bwf = g_adjbT[((b<<6) + jt*2 + (jq>>1))*NN + i0 + i];
        unsigned bw = (bwf >> ((jq & 1)*16)) & 0xFFFFu;
        const uint4* gp = &g2s[buf*32 + jq*8];
        #pragma unroll
        for (int pq = 0; pq < 2; pq++) {
            uint32_t wv[4];
            #pragma unroll
            for (int p = 0; p < 4; p++) {
                uint4 tr = gp[pq*4 + p];
                uint32_t mgt = hgt2m(tr.x, negg);
                uint32_t alt = hmul2u(rmulh, tr.z);
                uint32_t sel = (tr.y & mgt) | (alt & ~mgt);
                uint32_t bits = (bw >> ((pq*4 + p)*2)) & 3u;
                uint32_t am = ((bits & 1u) ? 0xFFFFu : 0u)
                            | ((bits & 2u) ? 0xFFFF0000u : 0u);
                wv[p] = sel & am;
            }
            uint32_t off = (uint32_t)i*144u + (uint32_t)(jq*32 + pq*16);
            *reinterpret_cast<uint4*>(Ahp + off) =
                make_uint4(wv[0], wv[1], wv[2], wv[3]);
        }
        {
            int c = t >> 3, ch = t & 7;
            uint4 v = *reinterpret_cast<const uint4*>(bsrc + (size_t)c*NN + j0 + ch*8);
            *reinterpret_cast<uint4*>(Bs + (uint32_t)c*144u + (uint32_t)ch*16u) = v;
        }
        if (jt < 31 && t < 32)
            g2s[(buf^1)*32 + t] = __ldg(&g2g[(jt+1)*32 + t]);
        __syncthreads();
        #pragma unroll
        for (int k = 0; k < 4; k++) {
            uint32_t kb = (uint32_t)k * 32u;
            uint32_t ah[4];
            ldsm_x4(ah, sbA + aRow + kb);
            mma16816h(accz, ah, bzf);
            uint32_t bf[4];
            ldsm_x4(bf, bAddr + kb);
            mma16816h(acc[0], ah, bf);
            mma16816h(acc[1], ah, bf + 2);
        }
    }
    float z0 = __shfl_sync(0xffffffffu, accz[0], lane & 28);
    float z1 = __shfl_sync(0xffffffffu, accz[2], lane & 28);
    if (z0 < 1e-30f) z0 = 1.f;
    if (z1 < 1e-30f) z1 = 1.f;
    float invz0 = 1.f / z0, invz1 = 1.f / z1;
    int r0 = mt*16 + (lane >> 2);
    int r1 = r0 + 8;
    #pragma unroll
    for (int n = 0; n < 2; n++) {
        int c0 = nh*16 + n*8 + (lane & 3)*2;
        float2 o0 = make_float2(acc[n][0]*invz0, acc[n][1]*invz0);
        float2 o1 = make_float2(acc[n][2]*invz1, acc[n][3]*invz1);
        *reinterpret_cast<float2*>(&out[(size_t)(b*NN + i0 + r0)*CC + c0]) = o0;
        *reinterpret_cast<float2*>(&out[(size_t)(b*NN + i0 + r1)*CC + c0]) = o1;
    }
}

extern "C" void kernel_launch(void* const* d_in, const int* in_sizes, int n_in,
                              void* d_out, int out_size) {
    const float* x   = (const float*)d_in[0];
    const int*   adj = (const int*)  d_in[1];
    const float* W   = (const float*)d_in[2];
    const float* a1  = (const float*)d_in[3];
    const float* a2  = (const float*)d_in[4];
    const float* Wo  = (const float*)d_in[5];
    const float* ao1 = (const float*)d_in[6];
    const float* ao2 = (const float*)d_in[7];
    float* out = (float*)d_out;

    cudaFuncSetAttribute(k3_attn1_mma,
                         cudaFuncAttributeMaxDynamicSharedMemorySize, K3_SMEM);
    cudaFuncSetAttribute(k1_hmma,
                         cudaFuncAttributeMaxDynamicSharedMemorySize, K1_SMEM);

    kws_split<<<64, 256>>>(W);                        // W -> WcatT fp16
    k4w_split<<<16, 256>>>(Wo);                       // Wo -> WoT fp16
    k0_mask<<<1024, 256>>>(adj);                      // adj -> transposed bitmask
    k1_hmma<<<dim3(8, 64), 256, K1_SMEM>>>(x, a1, a2);// Wh + WhT fp16 + f-triplets
    k3_attn1_mma<<<dim3(16, 8, 4), 256, K3_SMEM>>>(); // layer-1 attn (z via MMA)
    k4_hmma<<<128, 256>>>(ao1, ao2);                  // Wh2T fp16 + g-triplets
    k5_attn2_mma<<<dim3(32, 4), 256>>>(out);          // layer-2 attn (z via MMA)
}